// round 13
// baseline (speedup 1.0000x reference)
#include <cuda_runtime.h>
#include <cstdint>

#define KDIM 512
#define FDIM 512
#define BM   64
#define BN   32                  // W chunk width
#define NH_COLS 256              // N-half per tile
#define NTILES 2048              // (1024/BM) * 2 N-halves
#define GRID 296                 // 2 CTAs x 148 SMs, persistent

// smem layout (bytes)
#define SM_X    0                // 2 x (64 x 512) int8 double buffer, XOR-swizzled
#define XBUF    32768
#define SM_W    65536            // 2 x (32 x 512) int8 double buffer
#define WBUF    16384
#define SM_TAB  98304            // 256 x float4 {inv0, inv1, bias0, bias1}
#define SMEM_TOTAL 102400        // 100 KB -> 2 CTAs/SM

__device__ __align__(16) int8_t g_wq[FDIM * KDIM];   // [F][K]
__device__ float g_inv[FDIM];

__device__ __forceinline__ uint32_t smem_u32(const void* p) {
    uint32_t a;
    asm("{ .reg .u64 t; cvta.to.shared.u64 t, %1; cvt.u32.u64 %0, t; }" : "=r"(a) : "l"(p));
    return a;
}
__device__ __forceinline__ void cp_async16(uint32_t dst, const void* src) {
    asm volatile("cp.async.cg.shared.global [%0], [%1], 16;" :: "r"(dst), "l"(src));
}
__device__ __forceinline__ void ldsm_x4(uint32_t addr, unsigned& r0, unsigned& r1,
                                        unsigned& r2, unsigned& r3) {
    asm volatile("ldmatrix.sync.aligned.m8n8.x4.shared.b16 {%0,%1,%2,%3}, [%4];"
                 : "=r"(r0), "=r"(r1), "=r"(r2), "=r"(r3) : "r"(addr));
}
__device__ __forceinline__ unsigned quant_pack(float4 v) {
    const float A_SCALE = 127.0f / 3.0f;
    int q0 = max(-127, min(127, __float2int_rn(__fmul_rn(v.x, A_SCALE))));
    int q1 = max(-127, min(127, __float2int_rn(__fmul_rn(v.y, A_SCALE))));
    int q2 = max(-127, min(127, __float2int_rn(__fmul_rn(v.z, A_SCALE))));
    int q3 = max(-127, min(127, __float2int_rn(__fmul_rn(v.w, A_SCALE))));
    return (q0 & 0xff) | ((q1 & 0xff) << 8) | ((q2 & 0xff) << 16) |
           ((unsigned)(q3 & 0xff) << 24);
}

// ---------------------------------------------------------------------------
// Weight prequant: 32 blocks x 256 threads, 16 output-cols per block.
// ---------------------------------------------------------------------------
__global__ void quant_w_kernel(const float* __restrict__ kernel) {
    __shared__ float sm[512 * 17];
    __shared__ float red[16][16];
    __shared__ float sscale[16];
    const int j0 = blockIdx.x * 16;
    const int t  = threadIdx.x;

    #pragma unroll 4
    for (int i = 0; i < 32; ++i) {
        int idx = i * 256 + t;
        int k = idx >> 4, c = idx & 15;
        sm[k * 17 + c] = kernel[k * FDIM + j0 + c];
    }
    __syncthreads();
    {
        int c = t & 15, kr = t >> 4;
        float m = 0.f;
        #pragma unroll 8
        for (int i = 0; i < 32; ++i)
            m = fmaxf(m, fabsf(sm[(kr + i * 16) * 17 + c]));
        red[kr][c] = m;
    }
    __syncthreads();
    if (t < 16) {
        float m = red[0][t];
        #pragma unroll
        for (int r = 1; r < 16; ++r) m = fmaxf(m, red[r][t]);
        float s = __fdiv_rn(127.0f, fmaxf(m, 1e-7f));
        sscale[t] = s;
        const float A_SCALE = 127.0f / 3.0f;
        g_inv[j0 + t] = __fdiv_rn(1.0f, __fmul_rn(A_SCALE, s));
    }
    __syncthreads();

    const int w = t >> 5, lane = t & 31;
    #pragma unroll
    for (int cc = 0; cc < 2; ++cc) {
        int c = w * 2 + cc;
        float s = sscale[c];
        int kb = lane * 16;
        unsigned pk[4];
        #pragma unroll
        for (int i = 0; i < 4; ++i) {
            int q[4];
            #pragma unroll
            for (int jj = 0; jj < 4; ++jj) {
                float v = __fmul_rn(sm[(kb + i * 4 + jj) * 17 + c], s);
                int qi = __float2int_rn(v);
                q[jj] = max(-127, min(127, qi));
            }
            pk[i] = (q[0] & 0xff) | ((q[1] & 0xff) << 8) |
                    ((q[2] & 0xff) << 16) | ((unsigned)(q[3] & 0xff) << 24);
        }
        *(int4*)&g_wq[(size_t)(j0 + c) * KDIM + kb] =
            make_int4(pk[0], pk[1], pk[2], pk[3]);
    }
}

// ---------------------------------------------------------------------------
// Persistent fused GEMM, 64x256 tiles, deferred-by-one-chunk x quant+store
// (LDG latency fully hidden), W double-buffered via cp.async. 2 CTAs/SM.
// ---------------------------------------------------------------------------
__device__ __forceinline__ void load_w_async(uint32_t buf_u, int wc, int t) {
    const int8_t* base = g_wq + (size_t)wc * BN * KDIM;
    #pragma unroll
    for (int i = 0; i < 4; ++i) {
        int idx = i * 256 + t;               // 1024 16B-chunks
        int n = idx >> 5, c16 = idx & 31;
        uint32_t dst = buf_u + n * KDIM + ((c16 * 16) ^ ((n & 7) << 4));
        cp_async16(dst, base + n * KDIM + c16 * 16);
    }
    asm volatile("cp.async.commit_group;" ::: "memory");
}

__device__ __forceinline__ void store_share(int8_t* xbuf, int s, const float4* vx, int t) {
    #pragma unroll
    for (int k = 0; k < 4; ++k) {
        int idx = s * 1024 + k * 256 + t;    // float4 index in 64x128 grid
        int row = idx >> 7, c4 = idx & 127;
        *(unsigned*)&xbuf[row * KDIM +
            (((c4 * 4) & ~15) ^ ((row & 7) << 4)) + ((c4 & 3) * 4)] = quant_pack(vx[k]);
    }
}

__global__ void __launch_bounds__(256, 2)
gemm_kernel(const float* __restrict__ x, const float* __restrict__ bias,
            float* __restrict__ y) {
    extern __shared__ char smem[];
    int8_t* xs = (int8_t*)(smem + SM_X);
    float4* stab = (float4*)(smem + SM_TAB);

    const int t = threadIdx.x;
    const uint32_t xs_u = smem_u32(xs);
    const uint32_t ws_u = smem_u32(smem + SM_W);

    // this CTA's N-half is constant across all its tiles (GRID is even)
    const int nh = blockIdx.x & 1;
    const int wc0 = nh * 8;                  // first of its 8 W chunks

    // prime W chunk; overlaps tile-0 x-quant
    load_w_async(ws_u, wc0, t);

    // fused dequant table: {inv0, inv1, bias0, bias1} per column pair
    {
        int col = t * 2;
        stab[t] = make_float4(g_inv[col], g_inv[col + 1], bias[col], bias[col + 1]);
    }

    // tile-0 x-quant into xs buffer 0 (only DRAM-exposed quant phase)
    {
        const int r0 = (blockIdx.x >> 1) * BM;
        #pragma unroll 4
        for (int i = 0; i < 8; ++i) {
            int idx = i * 256 + t;
            int row = idx >> 5, c16 = idx & 31;
            const float4* src = (const float4*)(x + (size_t)(r0 + row) * KDIM + c16 * 16);
            unsigned pk[4];
            #pragma unroll
            for (int j = 0; j < 4; ++j) pk[j] = quant_pack(__ldg(src + j));
            *(uint4*)&xs[row * KDIM + ((c16 * 16) ^ ((row & 7) << 4))] =
                make_uint4(pk[0], pk[1], pk[2], pk[3]);
        }
    }

    const int warp = t >> 5, lane = t & 31;
    const int wm = warp >> 1, wn = warp & 1;     // 4 M-warps x 2 N-warps
    const int grp = lane >> 2, qid = lane & 3;
    const int mid  = lane >> 3;
    const int mrow = lane & 7;
    const int bsel = (mid >> 1) << 4;
    const uint32_t gxor = (uint32_t)mrow << 4;

    const uint32_t aoff = (uint32_t)(wm * 16 + (mid & 1) * 8 + mrow) * KDIM;
    const uint32_t bB   = ws_u + (uint32_t)(wn * 16 + (mid & 1) * 8 + mrow) * KDIM;

    float4 vx[4];
    bool not_first = false;
    int bx = 0;
    for (int tile = blockIdx.x; tile < NTILES; tile += GRID, bx ^= 1) {
        const int r0 = (tile >> 1) * BM;
        const int nxt_r0 = ((tile + GRID) >> 1) * BM;
        const bool pf = (tile + GRID) < NTILES;
        const uint32_t aA = xs_u + bx * XBUF + aoff;
        int8_t* xcurp = xs + bx * XBUF;
        int8_t* xnext = xs + (bx ^ 1) * XBUF;
        float* yr0 = y + (size_t)(r0 + wm * 16 + grp) * FDIM + nh * NH_COLS;

        for (int nb = 0; nb < 8; ++nb) {
            // W(nb) committed one chunk ago
            asm volatile("cp.async.wait_group 0;" ::: "memory");
            __syncthreads();
            load_w_async(ws_u + ((nb + 1) & 1) * WBUF, wc0 + ((nb + 1) & 7), t);

            // deferred quant+store of the share loaded one chunk ago
            if (nb == 0) {
                if (not_first) {
                    store_share(xcurp, 7, vx, t);    // share 7 -> current x buffer
                    __syncthreads();                 // visible before MMA reads it
                }
            } else if (pf) {
                store_share(xnext, nb - 1, vx, t);
            }

            // issue next-tile x loads (consumed one chunk later)
            if (pf) {
                #pragma unroll
                for (int k = 0; k < 4; ++k) {
                    int idx = nb * 1024 + k * 256 + t;
                    int xr = idx >> 7, xc = idx & 127;
                    vx[k] = __ldg((const float4*)(x + (size_t)(nxt_r0 + xr) * KDIM) + xc);
                }
            }

            const uint32_t bbase = bB + (nb & 1) * WBUF;

            int acc[2][4];
            #pragma unroll
            for (int nt = 0; nt < 2; ++nt)
                #pragma unroll
                for (int r = 0; r < 4; ++r) acc[nt][r] = 0;

            #pragma unroll
            for (int ks = 0; ks < 16; ++ks) {
                const uint32_t off = (uint32_t)(ks * 32 + bsel) ^ gxor;
                unsigned a[4], bb4[4];
                ldsm_x4(aA + off, a[0], a[1], a[2], a[3]);
                ldsm_x4(bbase + off, bb4[0], bb4[1], bb4[2], bb4[3]);
                asm volatile(
                    "mma.sync.aligned.m16n8k32.row.col.s32.s8.s8.s32 "
                    "{%0,%1,%2,%3},{%4,%5,%6,%7},{%8,%9},{%0,%1,%2,%3};\n"
                    : "+r"(acc[0][0]), "+r"(acc[0][1]), "+r"(acc[0][2]), "+r"(acc[0][3])
                    : "r"(a[0]), "r"(a[1]), "r"(a[2]), "r"(a[3]),
                      "r"(bb4[0]), "r"(bb4[2]));
                asm volatile(
                    "mma.sync.aligned.m16n8k32.row.col.s32.s8.s8.s32 "
                    "{%0,%1,%2,%3},{%4,%5,%6,%7},{%8,%9},{%0,%1,%2,%3};\n"
                    : "+r"(acc[1][0]), "+r"(acc[1][1]), "+r"(acc[1][2]), "+r"(acc[1][3])
                    : "r"(a[0]), "r"(a[1]), "r"(a[2]), "r"(a[3]),
                      "r"(bb4[1]), "r"(bb4[3]));
            }

            // epilogue: dequant + bias via fused float4 table, float2 stores
            #pragma unroll
            for (int nt = 0; nt < 2; ++nt) {
                int lcol = nb * BN + wn * 16 + nt * 8 + qid * 2;
                float4 tb = stab[(nh * NH_COLS + lcol) >> 1];
                float2 v0, v1;
                v0.x = (float)acc[nt][0] * tb.x + tb.z;
                v0.y = (float)acc[nt][1] * tb.y + tb.w;
                v1.x = (float)acc[nt][2] * tb.x + tb.z;
                v1.y = (float)acc[nt][3] * tb.y + tb.w;
                *(float2*)(yr0 + lcol) = v0;
                *(float2*)(yr0 + 8 * FDIM + lcol) = v1;
            }
        }
        not_first = true;
    }
    asm volatile("cp.async.wait_group 0;" ::: "memory");
}

// ---------------------------------------------------------------------------
extern "C" void kernel_launch(void* const* d_in, const int* in_sizes, int n_in,
                              void* d_out, int out_size) {
    const float* x    = (const float*)d_in[0];
    const float* kern = (const float*)d_in[1];
    const float* bias = (const float*)d_in[2];
    float* y = (float*)d_out;

    cudaFuncSetAttribute(gemm_kernel,
                         cudaFuncAttributeMaxDynamicSharedMemorySize, SMEM_TOTAL);

    quant_w_kernel<<<FDIM / 16, 256>>>(kern);
    gemm_kernel<<<GRID, 256, SMEM_TOTAL>>>(x, bias, y);
}

// round 17
// speedup vs baseline: 1.0739x; 1.0739x over previous
#include <cuda_runtime.h>
#include <cstdint>

#define KDIM 512
#define FDIM 512
#define BM   64
#define BN   32
#define NH_COLS 256
#define NTILES 2048
#define TENSOR_CTAS 148
#define GRID 296

// tensor-role smem layout
#define SM_X    0                // 2 x (64 x 512) int8, XOR-swizzled
#define XBUF    32768
#define SM_W    65536            // 2 x (32 x 512) int8
#define WBUF    16384
// dp4a-role smem layout (same allocation, different use)
#define SM_XD   0                // 64 x 528 int8
#define XD_PITCH 528
#define SM_WT   34816            // 2 x 16384 transposed W chunks
// shared
#define SM_TAB  98304            // 256 x float4 {inv0,inv1,bias0,bias1}
#define SM_CTL  102400           // tile-steal mailbox
#define SMEM_TOTAL 102416

__device__ __align__(16) int8_t g_wq[FDIM * KDIM];    // [F][K] for tensor path
__device__ __align__(16) int8_t g_wqT[FDIM * KDIM];   // [chunk][k_word][n] for dp4a
__device__ float g_inv[FDIM];
__device__ unsigned g_ctr;

__device__ __forceinline__ uint32_t smem_u32(const void* p) {
    uint32_t a;
    asm("{ .reg .u64 t; cvta.to.shared.u64 t, %1; cvt.u32.u64 %0, t; }" : "=r"(a) : "l"(p));
    return a;
}
__device__ __forceinline__ void cp_async16(uint32_t dst, const void* src) {
    asm volatile("cp.async.cg.shared.global [%0], [%1], 16;" :: "r"(dst), "l"(src));
}
__device__ __forceinline__ void ldsm_x4(uint32_t addr, unsigned& r0, unsigned& r1,
                                        unsigned& r2, unsigned& r3) {
    asm volatile("ldmatrix.sync.aligned.m8n8.x4.shared.b16 {%0,%1,%2,%3}, [%4];"
                 : "=r"(r0), "=r"(r1), "=r"(r2), "=r"(r3) : "r"(addr));
}
__device__ __forceinline__ unsigned quant_pack(float4 v) {
    const float A_SCALE = 127.0f / 3.0f;
    int q0 = max(-127, min(127, __float2int_rn(__fmul_rn(v.x, A_SCALE))));
    int q1 = max(-127, min(127, __float2int_rn(__fmul_rn(v.y, A_SCALE))));
    int q2 = max(-127, min(127, __float2int_rn(__fmul_rn(v.z, A_SCALE))));
    int q3 = max(-127, min(127, __float2int_rn(__fmul_rn(v.w, A_SCALE))));
    return (q0 & 0xff) | ((q1 & 0xff) << 8) | ((q2 & 0xff) << 16) |
           ((unsigned)(q3 & 0xff) << 24);
}

// ---------------------------------------------------------------------------
// Weight prequant -> g_wq (K-major rows) AND g_wqT (k_word-major for dp4a).
// Also resets the tile-steal counter each replay.
// ---------------------------------------------------------------------------
__global__ void quant_w_kernel(const float* __restrict__ kernel) {
    if (blockIdx.x == 0 && threadIdx.x == 0) g_ctr = 0;
    __shared__ float sm[512 * 17];
    __shared__ float red[16][16];
    __shared__ float sscale[16];
    const int j0 = blockIdx.x * 16;
    const int t  = threadIdx.x;

    #pragma unroll 4
    for (int i = 0; i < 32; ++i) {
        int idx = i * 256 + t;
        int k = idx >> 4, c = idx & 15;
        sm[k * 17 + c] = kernel[k * FDIM + j0 + c];
    }
    __syncthreads();
    {
        int c = t & 15, kr = t >> 4;
        float m = 0.f;
        #pragma unroll 8
        for (int i = 0; i < 32; ++i)
            m = fmaxf(m, fabsf(sm[(kr + i * 16) * 17 + c]));
        red[kr][c] = m;
    }
    __syncthreads();
    if (t < 16) {
        float m = red[0][t];
        #pragma unroll
        for (int r = 1; r < 16; ++r) m = fmaxf(m, red[r][t]);
        float s = __fdiv_rn(127.0f, fmaxf(m, 1e-7f));
        sscale[t] = s;
        const float A_SCALE = 127.0f / 3.0f;
        g_inv[j0 + t] = __fdiv_rn(1.0f, __fmul_rn(A_SCALE, s));
    }
    __syncthreads();

    const int w = t >> 5, lane = t & 31;
    #pragma unroll
    for (int cc = 0; cc < 2; ++cc) {
        int c = w * 2 + cc;
        int gc = j0 + c;
        float s = sscale[c];
        int kb = lane * 16;
        unsigned pk[4];
        #pragma unroll
        for (int i = 0; i < 4; ++i) {
            int q[4];
            #pragma unroll
            for (int jj = 0; jj < 4; ++jj) {
                float v = __fmul_rn(sm[(kb + i * 4 + jj) * 17 + c], s);
                int qi = __float2int_rn(v);
                q[jj] = max(-127, min(127, qi));
            }
            pk[i] = (q[0] & 0xff) | ((q[1] & 0xff) << 8) |
                    ((q[2] & 0xff) << 16) | ((unsigned)(q[3] & 0xff) << 24);
        }
        *(int4*)&g_wq[(size_t)gc * KDIM + kb] = make_int4(pk[0], pk[1], pk[2], pk[3]);
        // transposed image: chunk=gc/32, rows of 32 cols x 4B at each k_word
        #pragma unroll
        for (int i = 0; i < 4; ++i)
            *(unsigned*)&g_wqT[(size_t)(gc >> 5) * 16384 + (lane * 4 + i) * 128 +
                               (gc & 31) * 4] = pk[i];
    }
}

// ---------------------------------------------------------------------------
__device__ __forceinline__ void load_w_async(uint32_t buf_u, int wc, int t) {
    const int8_t* base = g_wq + (size_t)wc * BN * KDIM;
    #pragma unroll
    for (int i = 0; i < 4; ++i) {
        int idx = i * 256 + t;
        int n = idx >> 5, c16 = idx & 31;
        uint32_t dst = buf_u + n * KDIM + ((c16 * 16) ^ ((n & 7) << 4));
        cp_async16(dst, base + n * KDIM + c16 * 16);
    }
    asm volatile("cp.async.commit_group;" ::: "memory");
}
__device__ __forceinline__ void load_wT_async(uint32_t buf_u, int wc, int t) {
    const int8_t* base = g_wqT + (size_t)wc * 16384;
    #pragma unroll
    for (int i = 0; i < 4; ++i) {
        int idx = i * 256 + t;
        cp_async16(buf_u + idx * 16, base + idx * 16);
    }
    asm volatile("cp.async.commit_group;" ::: "memory");
}

#define DPQ(ac, xw, wq) { ac[0]=__dp4a((int)(xw),(int)(wq).x,ac[0]); \
                          ac[1]=__dp4a((int)(xw),(int)(wq).y,ac[1]); \
                          ac[2]=__dp4a((int)(xw),(int)(wq).z,ac[2]); \
                          ac[3]=__dp4a((int)(xw),(int)(wq).w,ac[3]); }

__global__ void __launch_bounds__(256, 2)
gemm_kernel(const float* __restrict__ x, const float* __restrict__ bias,
            float* __restrict__ y) {
    extern __shared__ char smem[];
    float4* stab = (float4*)(smem + SM_TAB);
    volatile unsigned* ctl = (volatile unsigned*)(smem + SM_CTL);

    const int t = threadIdx.x;
    const float A_SCALE = 127.0f / 3.0f;
    {
        int col = t * 2;
        stab[t] = make_float4(g_inv[col], g_inv[col + 1], bias[col], bias[col + 1]);
    }
    if (t == 0) *ctl = atomicAdd(&g_ctr, 1u);
    __syncthreads();
    unsigned cur = *ctl;

    if (blockIdx.x < TENSOR_CTAS) {
        // ================= TENSOR ROLE =================
        int8_t* xs = (int8_t*)(smem + SM_X);
        const uint32_t xs_u = smem_u32(xs);
        const uint32_t ws_u = smem_u32(smem + SM_W);

        const int warp = t >> 5, lane = t & 31;
        const int wm = warp >> 1, wn = warp & 1;
        const int grp = lane >> 2, qid = lane & 3;
        const int mid  = lane >> 3, mrow = lane & 7;
        const int bsel = (mid >> 1) << 4;
        const uint32_t gxor = (uint32_t)mrow << 4;
        const uint32_t aoff = (uint32_t)(wm * 16 + (mid & 1) * 8 + mrow) * KDIM;
        const uint32_t bB   = ws_u + (uint32_t)(wn * 16 + (mid & 1) * 8 + mrow) * KDIM;

        if (cur < NTILES) {   // prologue: prime W + quant x for first tile
            int r0 = (int)(cur >> 1) * BM, nh = cur & 1;
            load_w_async(ws_u, nh * 8, t);
            #pragma unroll 4
            for (int i = 0; i < 8; ++i) {
                int idx = i * 256 + t;
                int row = idx >> 5, c16 = idx & 31;
                const float4* src = (const float4*)(x + (size_t)(r0 + row) * KDIM + c16 * 16);
                unsigned pk[4];
                #pragma unroll
                for (int j = 0; j < 4; ++j) pk[j] = quant_pack(__ldg(src + j));
                *(uint4*)&xs[row * KDIM + ((c16 * 16) ^ ((row & 7) << 4))] =
                    make_uint4(pk[0], pk[1], pk[2], pk[3]);
            }
        }

        int bx = 0;
        while (cur < NTILES) {
            const int r0 = (int)(cur >> 1) * BM;
            const int nh = cur & 1;
            if (t == 0) *ctl = atomicAdd(&g_ctr, 1u);
            unsigned nxt = 0; bool pf = false; int nxt_r0 = 0, nxt_nh = 0;
            const uint32_t aA = xs_u + bx * XBUF + aoff;
            int8_t* xnext = xs + (bx ^ 1) * XBUF;
            float* yr0 = y + (size_t)(r0 + wm * 16 + grp) * FDIM + nh * NH_COLS;

            for (int nb = 0; nb < 8; ++nb) {
                asm volatile("cp.async.wait_group 0;" ::: "memory");
                __syncthreads();
                if (nb == 0) {
                    nxt = *ctl; pf = nxt < NTILES;
                    nxt_r0 = (int)(nxt >> 1) * BM; nxt_nh = nxt & 1;
                }
                if (nb < 7)
                    load_w_async(ws_u + ((nb + 1) & 1) * WBUF, nh * 8 + nb + 1, t);
                else if (pf)
                    load_w_async(ws_u + ((nb + 1) & 1) * WBUF, nxt_nh * 8, t);

                float4 vx[4]; int xrow[4], xc4[4];
                if (pf) {
                    #pragma unroll
                    for (int k = 0; k < 4; ++k) {
                        int idx = nb * 1024 + k * 256 + t;
                        xrow[k] = idx >> 7; xc4[k] = idx & 127;
                        vx[k] = __ldg((const float4*)(x + (size_t)(nxt_r0 + xrow[k]) * KDIM)
                                      + xc4[k]);
                    }
                }

                const uint32_t bbase = bB + (nb & 1) * WBUF;
                int acc[2][4];
                #pragma unroll
                for (int nt = 0; nt < 2; ++nt)
                    #pragma unroll
                    for (int r = 0; r < 4; ++r) acc[nt][r] = 0;

                #pragma unroll
                for (int ks = 0; ks < 16; ++ks) {
                    const uint32_t off = (uint32_t)(ks * 32 + bsel) ^ gxor;
                    unsigned a[4], bb4[4];
                    ldsm_x4(aA + off, a[0], a[1], a[2], a[3]);
                    ldsm_x4(bbase + off, bb4[0], bb4[1], bb4[2], bb4[3]);
                    asm volatile(
                        "mma.sync.aligned.m16n8k32.row.col.s32.s8.s8.s32 "
                        "{%0,%1,%2,%3},{%4,%5,%6,%7},{%8,%9},{%0,%1,%2,%3};\n"
                        : "+r"(acc[0][0]), "+r"(acc[0][1]), "+r"(acc[0][2]), "+r"(acc[0][3])
                        : "r"(a[0]), "r"(a[1]), "r"(a[2]), "r"(a[3]),
                          "r"(bb4[0]), "r"(bb4[2]));
                    asm volatile(
                        "mma.sync.aligned.m16n8k32.row.col.s32.s8.s8.s32 "
                        "{%0,%1,%2,%3},{%4,%5,%6,%7},{%8,%9},{%0,%1,%2,%3};\n"
                        : "+r"(acc[1][0]), "+r"(acc[1][1]), "+r"(acc[1][2]), "+r"(acc[1][3])
                        : "r"(a[0]), "r"(a[1]), "r"(a[2]), "r"(a[3]),
                          "r"(bb4[1]), "r"(bb4[3]));
                }

                if (pf) {
                    #pragma unroll
                    for (int k = 0; k < 4; ++k)
                        *(unsigned*)&xnext[xrow[k] * KDIM +
                            (((xc4[k] * 4) & ~15) ^ ((xrow[k] & 7) << 4)) +
                            ((xc4[k] & 3) * 4)] = quant_pack(vx[k]);
                }

                #pragma unroll
                for (int nt = 0; nt < 2; ++nt) {
                    int lcol = nb * BN + wn * 16 + nt * 8 + qid * 2;
                    float4 tb = stab[(nh * NH_COLS + lcol) >> 1];
                    float2 v0, v1;
                    v0.x = (float)acc[nt][0] * tb.x + tb.z;
                    v0.y = (float)acc[nt][1] * tb.y + tb.w;
                    v1.x = (float)acc[nt][2] * tb.x + tb.z;
                    v1.y = (float)acc[nt][3] * tb.y + tb.w;
                    *(float2*)(yr0 + lcol) = v0;
                    *(float2*)(yr0 + 8 * FDIM + lcol) = v1;
                }
            }
            cur = nxt; bx ^= 1;
        }
        asm volatile("cp.async.wait_group 0;" ::: "memory");
    } else {
        // ================= DP4A ROLE =================
        int8_t* xsd = (int8_t*)(smem + SM_XD);
        const uint32_t wt_u = smem_u32(smem + SM_WT);
        const int n4 = t & 7;          // cols n4*4..+3 within 32-col chunk
        const int m2 = t >> 3;         // rows 2*m2, 2*m2+1
        bool first = true;

        while (cur < NTILES) {
            const int r0 = (int)(cur >> 1) * BM;
            const int nh = cur & 1;
            if (first) { load_wT_async(wt_u, nh * 8, t); first = false; }
            __syncthreads();           // prev-tile readers done with xsd

            #pragma unroll 2
            for (int i = 0; i < 8; ++i) {
                int idx = i * 256 + t;
                int row = idx >> 5, c16 = idx & 31;
                const float4* src = (const float4*)(x + (size_t)(r0 + row) * KDIM + c16 * 16);
                unsigned pk[4];
                #pragma unroll
                for (int j = 0; j < 4; ++j) pk[j] = quant_pack(__ldg(src + j));
                *(uint4*)&xsd[row * XD_PITCH + c16 * 16] =
                    make_uint4(pk[0], pk[1], pk[2], pk[3]);
            }
            if (t == 0) *ctl = atomicAdd(&g_ctr, 1u);
            unsigned nxt = 0; bool pf = false; int nxt_nh = 0;

            for (int nb = 0; nb < 8; ++nb) {
                asm volatile("cp.async.wait_group 0;" ::: "memory");
                __syncthreads();
                if (nb == 0) { nxt = *ctl; pf = nxt < NTILES; nxt_nh = nxt & 1; }
                if (nb < 7)
                    load_wT_async(wt_u + ((nb + 1) & 1) * WBUF, nh * 8 + nb + 1, t);
                else if (pf)
                    load_wT_async(wt_u, nxt_nh * 8, t);

                const char* wb = smem + SM_WT + (nb & 1) * WBUF + n4 * 16;
                const char* xb = (const char*)xsd + (m2 * 2) * XD_PITCH;
                int a0[4] = {0, 0, 0, 0}, a1[4] = {0, 0, 0, 0};

                #pragma unroll 4
                for (int k16 = 0; k16 < 32; ++k16) {
                    uint4 x0 = *(const uint4*)(xb + k16 * 16);
                    uint4 x1 = *(const uint4*)(xb + XD_PITCH + k16 * 16);
                    uint4 w0 = *(const uint4*)(wb + (k16 * 4 + 0) * 128);
                    uint4 w1 = *(const uint4*)(wb + (k16 * 4 + 1) * 128);
                    uint4 w2 = *(const uint4*)(wb + (k16 * 4 + 2) * 128);
                    uint4 w3 = *(const uint4*)(wb + (k16 * 4 + 3) * 128);
                    DPQ(a0, x0.x, w0) DPQ(a0, x0.y, w1) DPQ(a0, x0.z, w2) DPQ(a0, x0.w, w3)
                    DPQ(a1, x1.x, w0) DPQ(a1, x1.y, w1) DPQ(a1, x1.z, w2) DPQ(a1, x1.w, w3)
                }

                const int colb = nh * NH_COLS + nb * BN + n4 * 4;
                float4 tb0 = stab[colb >> 1], tb1 = stab[(colb >> 1) + 1];
                float* yp = y + (size_t)(r0 + m2 * 2) * FDIM + colb;
                float4 o0, o1;
                o0.x = (float)a0[0] * tb0.x + tb0.z;
                o0.y = (float)a0[1] * tb0.y + tb0.w;
                o0.z = (float)a0[2] * tb1.x + tb1.z;
                o0.w = (float)a0[3] * tb1.y + tb1.w;
                o1.x = (float)a1[0] * tb0.x + tb0.z;
                o1.y = (float)a1[1] * tb0.y + tb0.w;
                o1.z = (float)a1[2] * tb1.x + tb1.z;
                o1.w = (float)a1[3] * tb1.y + tb1.w;
                *(float4*)yp = o0;
                *(float4*)(yp + FDIM) = o1;
            }
            cur = nxt;
        }
        asm volatile("cp.async.wait_group 0;" ::: "memory");
    }
}

// ---------------------------------------------------------------------------
extern "C" void kernel_launch(void* const* d_in, const int* in_sizes, int n_in,
                              void* d_out, int out_size) {
    const float* x    = (const float*)d_in[0];
    const float* kern = (const float*)d_in[1];
    const float* bias = (const float*)d_in[2];
    float* y = (float*)d_out;

    cudaFuncSetAttribute(gemm_kernel,
                         cudaFuncAttributeMaxDynamicSharedMemorySize, SMEM_TOTAL);

    quant_w_kernel<<<FDIM / 16, 256>>>(kern);
    gemm_kernel<<<GRID, 256, SMEM_TOTAL>>>(x, bias, y);
}